// round 2
// baseline (speedup 1.0000x reference)
#include <cuda_runtime.h>
#include <math.h>

#define N_NODES 100000
#define N_EDGES 1600000
#define F_IN 50
#define NC 32

// Scratch (device globals — no allocation allowed)
__device__ float g_agg[N_NODES * F_IN];   // aggregation buffer (max dim 50)
__device__ float g_h1[N_NODES * NC];
__device__ float g_h2[N_NODES * NC];
__device__ int   g_src[N_EDGES];
__device__ int   g_dst[N_EDGES];
__device__ int   g_is64;

__device__ __forceinline__ void atomicMaxF(float* addr, float v) {
    // Monotone-bit trick: valid given init = -inf (0xFF800000)
    if (v >= 0.0f) {
        atomicMax((int*)addr, __float_as_int(v));
    } else {
        atomicMin((unsigned int*)addr, __float_as_uint(v));
    }
}

// Detect whether the edge buffer is int64 (odd 32-bit words all zero) or int32.
__global__ void detect_dtype_kernel(const int* __restrict__ ei_raw) {
    int allzero = 1;
    for (int i = 0; i < 64; i++) {
        if (ei_raw[2 * i + 1] != 0) { allzero = 0; break; }
    }
    g_is64 = allzero;
}

__global__ void convert_edges_kernel(const void* __restrict__ ei_raw,
                                     int* __restrict__ src, int* __restrict__ dst) {
    int i = blockIdx.x * blockDim.x + threadIdx.x;
    if (i >= N_EDGES) return;
    if (g_is64) {
        const long long* p = (const long long*)ei_raw;
        src[i] = (int)p[i];
        dst[i] = (int)p[N_EDGES + i];
    } else {
        const int* p = (const int*)ei_raw;
        src[i] = p[i];
        dst[i] = p[N_EDGES + i];
    }
}

__global__ void init_neg_inf(float* buf, int n) {
    int i = blockIdx.x * blockDim.x + threadIdx.x;
    if (i < n) buf[i] = __int_as_float(0xFF800000);  // -inf
}

// One TPE-thread slice per edge. Coalesced gather of x[src] row, coalesced atomics to agg[dst] row.
template <int F, int TPE>
__global__ void scatter_max_kernel(const float* __restrict__ x,
                                   const int* __restrict__ src_idx,
                                   const int* __restrict__ dst_idx,
                                   float* __restrict__ agg) {
    constexpr int EPB = 256 / TPE;  // edges per block
    int e = blockIdx.x * EPB + threadIdx.x / TPE;
    int f = threadIdx.x % TPE;
    if (e >= N_EDGES) return;
    int src = src_idx[e];
    int dst = dst_idx[e];
    if (f < F) {
        float v = x[src * F + f];
        atomicMaxF(&agg[dst * F + f], v);
    }
}

__device__ __forceinline__ float fix_neg_inf(float a) {
    // only -inf can appear (empty segment); exact bit check, fast-math safe
    return (__float_as_int(a) == (int)0xFF800000) ? 0.0f : a;
}

// out[r][c] = act( fix(agg[r]) @ Wl + bl + xin[r] @ Wr ), one warp per row, lane = col
template <int F, bool RELU>
__global__ void sage_linear_kernel(const float* __restrict__ agg,
                                   const float* __restrict__ xin,
                                   const float* __restrict__ Wl,
                                   const float* __restrict__ bl,
                                   const float* __restrict__ Wr,
                                   float* __restrict__ out) {
    __shared__ float sWl[F][NC];
    __shared__ float sWr[F][NC];
    int tid = threadIdx.x;  // 256
    for (int i = tid; i < F * NC; i += 256) {
        sWl[i / NC][i % NC] = Wl[i];
        sWr[i / NC][i % NC] = Wr[i];
    }
    __syncthreads();
    int r = blockIdx.x * 8 + (tid >> 5);
    int c = tid & 31;
    if (r >= N_NODES) return;
    float acc = bl[c];
    const float* ar = agg + r * F;
    const float* xr = xin + r * F;
#pragma unroll
    for (int k = 0; k < F; k++) {
        acc += fix_neg_inf(ar[k]) * sWl[k][c] + xr[k] * sWr[k][c];
    }
    if (RELU) acc = fmaxf(acc, 0.0f);
    out[r * NC + c] = acc;
}

// Final layer: linear (no relu) + log_softmax over the 32 cols (warp-wide)
template <int F>
__global__ void sage_linear_lsm_kernel(const float* __restrict__ agg,
                                       const float* __restrict__ xin,
                                       const float* __restrict__ Wl,
                                       const float* __restrict__ bl,
                                       const float* __restrict__ Wr,
                                       float* __restrict__ out) {
    __shared__ float sWl[F][NC];
    __shared__ float sWr[F][NC];
    int tid = threadIdx.x;
    for (int i = tid; i < F * NC; i += 256) {
        sWl[i / NC][i % NC] = Wl[i];
        sWr[i / NC][i % NC] = Wr[i];
    }
    __syncthreads();
    int r = blockIdx.x * 8 + (tid >> 5);
    int c = tid & 31;
    if (r >= N_NODES) return;
    float acc = bl[c];
    const float* ar = agg + r * F;
    const float* xr = xin + r * F;
#pragma unroll
    for (int k = 0; k < F; k++) {
        acc += fix_neg_inf(ar[k]) * sWl[k][c] + xr[k] * sWr[k][c];
    }
    // log_softmax across the 32 lanes of this warp
    float m = acc;
#pragma unroll
    for (int o = 16; o; o >>= 1) m = fmaxf(m, __shfl_xor_sync(0xffffffff, m, o));
    float ex = __expf(acc - m);
    float s = ex;
#pragma unroll
    for (int o = 16; o; o >>= 1) s += __shfl_xor_sync(0xffffffff, s, o);
    out[r * NC + c] = acc - m - __logf(s);
}

extern "C" void kernel_launch(void* const* d_in, const int* in_sizes, int n_in,
                              void* d_out, int out_size) {
    const float* x = (const float*)d_in[0];
    const void* ei = d_in[1];
    const float* Wl1 = (const float*)d_in[2];
    const float* bl1 = (const float*)d_in[3];
    const float* Wr1 = (const float*)d_in[4];
    const float* Wl2 = (const float*)d_in[5];
    const float* bl2 = (const float*)d_in[6];
    const float* Wr2 = (const float*)d_in[7];
    const float* Wl3 = (const float*)d_in[8];
    const float* bl3 = (const float*)d_in[9];
    const float* Wr3 = (const float*)d_in[10];
    float* out = (float*)d_out;

    float *agg, *h1, *h2;
    int *src, *dst;
    cudaGetSymbolAddress((void**)&agg, g_agg);
    cudaGetSymbolAddress((void**)&h1, g_h1);
    cudaGetSymbolAddress((void**)&h2, g_h2);
    cudaGetSymbolAddress((void**)&src, g_src);
    cudaGetSymbolAddress((void**)&dst, g_dst);

    const int lin_blocks = (N_NODES + 7) / 8;

    // ---- Edge index normalization (dtype-robust) ----
    detect_dtype_kernel<<<1, 1>>>((const int*)ei);
    convert_edges_kernel<<<(N_EDGES + 255) / 256, 256>>>(ei, src, dst);

    // ---- Layer 1 (F=50) ----
    {
        int n = N_NODES * F_IN;
        init_neg_inf<<<(n + 255) / 256, 256>>>(agg, n);
        int blocks = (N_EDGES + 3) / 4;  // EPB=4 @ TPE=64
        scatter_max_kernel<F_IN, 64><<<blocks, 256>>>(x, src, dst, agg);
        sage_linear_kernel<F_IN, true><<<lin_blocks, 256>>>(agg, x, Wl1, bl1, Wr1, h1);
    }
    // ---- Layer 2 (F=32) ----
    {
        int n = N_NODES * NC;
        init_neg_inf<<<(n + 255) / 256, 256>>>(agg, n);
        int blocks = (N_EDGES + 7) / 8;  // EPB=8 @ TPE=32
        scatter_max_kernel<NC, 32><<<blocks, 256>>>(h1, src, dst, agg);
        sage_linear_kernel<NC, true><<<lin_blocks, 256>>>(agg, h1, Wl2, bl2, Wr2, h2);
    }
    // ---- Layer 3 (F=32) + log_softmax ----
    {
        int n = N_NODES * NC;
        init_neg_inf<<<(n + 255) / 256, 256>>>(agg, n);
        int blocks = (N_EDGES + 7) / 8;
        scatter_max_kernel<NC, 32><<<blocks, 256>>>(h2, src, dst, agg);
        sage_linear_lsm_kernel<NC><<<lin_blocks, 256>>>(agg, h2, Wl3, bl3, Wr3, out);
    }
}

// round 3
// speedup vs baseline: 1.9612x; 1.9612x over previous
#include <cuda_runtime.h>
#include <math.h>

#define N_NODES 100000
#define N_EDGES 1600000
#define F_IN 50
#define NC 32
#define NEG_INF __int_as_float(0xFF800000)

// ---- Scratch (device globals — no allocation allowed) ----
__device__ float g_agg[N_NODES * F_IN];
__device__ float g_h1[N_NODES * NC];
__device__ float g_h2[N_NODES * NC];
__device__ int   g_src[N_EDGES];
__device__ int   g_dst[N_EDGES];
__device__ int   g_csr_src[N_EDGES];
__device__ int   g_deg[N_NODES];
__device__ int   g_rowptr[N_NODES];
__device__ int   g_cursor[N_NODES];
__device__ int   g_excl[N_NODES];
__device__ int   g_bsums[256];
__device__ int   g_is64;

// ---- Edge dtype normalization ----
__global__ void detect_dtype_kernel(const int* __restrict__ ei_raw) {
    int allzero = 1;
    for (int i = 0; i < 64; i++)
        if (ei_raw[2 * i + 1] != 0) { allzero = 0; break; }
    g_is64 = allzero;
}

__global__ void convert_edges_kernel(const void* __restrict__ ei_raw,
                                     int* __restrict__ src, int* __restrict__ dst) {
    int i = blockIdx.x * blockDim.x + threadIdx.x;
    if (i >= N_EDGES) return;
    if (g_is64) {
        const long long* p = (const long long*)ei_raw;
        src[i] = (int)p[i];
        dst[i] = (int)p[N_EDGES + i];
    } else {
        const int* p = (const int*)ei_raw;
        src[i] = p[i];
        dst[i] = p[N_EDGES + i];
    }
}

// ---- CSR build: histogram -> exclusive scan -> bucket scatter ----
__global__ void zero_deg_kernel(int* __restrict__ deg) {
    int i = blockIdx.x * blockDim.x + threadIdx.x;
    if (i < N_NODES) deg[i] = 0;
}

__global__ void histogram_kernel(const int* __restrict__ dst, int* __restrict__ deg) {
    int i = blockIdx.x * blockDim.x + threadIdx.x;
    if (i < N_EDGES) atomicAdd(&deg[dst[i]], 1);
}

#define SCAN_BS 512
__global__ void scan_partial_kernel(const int* __restrict__ deg,
                                    int* __restrict__ excl, int* __restrict__ bsums) {
    __shared__ int s[SCAN_BS];
    int i = blockIdx.x * SCAN_BS + threadIdx.x;
    int v = (i < N_NODES) ? deg[i] : 0;
    s[threadIdx.x] = v;
    __syncthreads();
    for (int off = 1; off < SCAN_BS; off <<= 1) {
        int t = (threadIdx.x >= off) ? s[threadIdx.x - off] : 0;
        __syncthreads();
        s[threadIdx.x] += t;
        __syncthreads();
    }
    if (i < N_NODES) excl[i] = s[threadIdx.x] - v;
    if (threadIdx.x == SCAN_BS - 1) bsums[blockIdx.x] = s[SCAN_BS - 1];
}

__global__ void scan_bsums_kernel(int* __restrict__ bsums, int nb) {
    __shared__ int s[256];
    int t = threadIdx.x;
    s[t] = (t < nb) ? bsums[t] : 0;
    __syncthreads();
    if (t == 0) {
        int acc = 0;
        for (int i = 0; i < nb; i++) { int v = s[i]; s[i] = acc; acc += v; }
    }
    __syncthreads();
    if (t < nb) bsums[t] = s[t];
}

__global__ void scan_finish_kernel(const int* __restrict__ excl, const int* __restrict__ bsums,
                                   int* __restrict__ rowptr, int* __restrict__ cursor) {
    int i = blockIdx.x * blockDim.x + threadIdx.x;
    if (i >= N_NODES) return;
    int v = excl[i] + bsums[i / SCAN_BS];
    rowptr[i] = v;
    cursor[i] = v;
}

__global__ void bucket_scatter_kernel(const int* __restrict__ src, const int* __restrict__ dst,
                                      int* __restrict__ cursor, int* __restrict__ csr_src) {
    int i = blockIdx.x * blockDim.x + threadIdx.x;
    if (i >= N_EDGES) return;
    int pos = atomicAdd(&cursor[dst[i]], 1);
    csr_src[pos] = src[i];
}

// ---- Aggregation: TPN-thread group per node, lane = feature, gather-max ----
template <int F, int TPN>
__global__ void csr_max_kernel(const float* __restrict__ x,
                               const int* __restrict__ rowptr,
                               const int* __restrict__ deg,
                               const int* __restrict__ csr_src,
                               float* __restrict__ agg) {
    constexpr int NPB = 256 / TPN;
    int node = blockIdx.x * NPB + threadIdx.x / TPN;
    int f = threadIdx.x % TPN;
    if (node >= N_NODES) return;
    int start = rowptr[node];
    int d = deg[node];
    float v = NEG_INF;
    if (f < F) {
        int j = 0;
        for (; j + 4 <= d; j += 4) {
            int s0 = csr_src[start + j];
            int s1 = csr_src[start + j + 1];
            int s2 = csr_src[start + j + 2];
            int s3 = csr_src[start + j + 3];
            float a = x[s0 * F + f];
            float b = x[s1 * F + f];
            float c = x[s2 * F + f];
            float e = x[s3 * F + f];
            v = fmaxf(v, fmaxf(fmaxf(a, b), fmaxf(c, e)));
        }
        for (; j < d; j++) v = fmaxf(v, x[csr_src[start + j] * F + f]);
        agg[node * F + f] = (d == 0) ? 0.0f : v;
    }
}

// ---- out[r][c] = act( agg[r] @ Wl + bl + xin[r] @ Wr ), warp/row, lane=col ----
template <int F, bool RELU>
__global__ void sage_linear_kernel(const float* __restrict__ agg,
                                   const float* __restrict__ xin,
                                   const float* __restrict__ Wl,
                                   const float* __restrict__ bl,
                                   const float* __restrict__ Wr,
                                   float* __restrict__ out) {
    __shared__ float sWl[F][NC];
    __shared__ float sWr[F][NC];
    int tid = threadIdx.x;  // 256
    for (int i = tid; i < F * NC; i += 256) {
        sWl[i / NC][i % NC] = Wl[i];
        sWr[i / NC][i % NC] = Wr[i];
    }
    __syncthreads();
    int r = blockIdx.x * 8 + (tid >> 5);
    int c = tid & 31;
    if (r >= N_NODES) return;
    float acc = bl[c];
    const float* ar = agg + r * F;
    const float* xr = xin + r * F;
#pragma unroll
    for (int k = 0; k < F; k++)
        acc += ar[k] * sWl[k][c] + xr[k] * sWr[k][c];
    if (RELU) acc = fmaxf(acc, 0.0f);
    out[r * NC + c] = acc;
}

template <int F>
__global__ void sage_linear_lsm_kernel(const float* __restrict__ agg,
                                       const float* __restrict__ xin,
                                       const float* __restrict__ Wl,
                                       const float* __restrict__ bl,
                                       const float* __restrict__ Wr,
                                       float* __restrict__ out) {
    __shared__ float sWl[F][NC];
    __shared__ float sWr[F][NC];
    int tid = threadIdx.x;
    for (int i = tid; i < F * NC; i += 256) {
        sWl[i / NC][i % NC] = Wl[i];
        sWr[i / NC][i % NC] = Wr[i];
    }
    __syncthreads();
    int r = blockIdx.x * 8 + (tid >> 5);
    int c = tid & 31;
    if (r >= N_NODES) return;
    float acc = bl[c];
    const float* ar = agg + r * F;
    const float* xr = xin + r * F;
#pragma unroll
    for (int k = 0; k < F; k++)
        acc += ar[k] * sWl[k][c] + xr[k] * sWr[k][c];
    float m = acc;
#pragma unroll
    for (int o = 16; o; o >>= 1) m = fmaxf(m, __shfl_xor_sync(0xffffffff, m, o));
    float ex = __expf(acc - m);
    float s = ex;
#pragma unroll
    for (int o = 16; o; o >>= 1) s += __shfl_xor_sync(0xffffffff, s, o);
    out[r * NC + c] = acc - m - __logf(s);
}

extern "C" void kernel_launch(void* const* d_in, const int* in_sizes, int n_in,
                              void* d_out, int out_size) {
    const float* x = (const float*)d_in[0];
    const void* ei = d_in[1];
    const float* Wl1 = (const float*)d_in[2];
    const float* bl1 = (const float*)d_in[3];
    const float* Wr1 = (const float*)d_in[4];
    const float* Wl2 = (const float*)d_in[5];
    const float* bl2 = (const float*)d_in[6];
    const float* Wr2 = (const float*)d_in[7];
    const float* Wl3 = (const float*)d_in[8];
    const float* bl3 = (const float*)d_in[9];
    const float* Wr3 = (const float*)d_in[10];
    float* out = (float*)d_out;

    float *agg, *h1, *h2;
    int *src, *dst, *csr_src, *deg, *rowptr, *cursor, *excl, *bsums;
    cudaGetSymbolAddress((void**)&agg, g_agg);
    cudaGetSymbolAddress((void**)&h1, g_h1);
    cudaGetSymbolAddress((void**)&h2, g_h2);
    cudaGetSymbolAddress((void**)&src, g_src);
    cudaGetSymbolAddress((void**)&dst, g_dst);
    cudaGetSymbolAddress((void**)&csr_src, g_csr_src);
    cudaGetSymbolAddress((void**)&deg, g_deg);
    cudaGetSymbolAddress((void**)&rowptr, g_rowptr);
    cudaGetSymbolAddress((void**)&cursor, g_cursor);
    cudaGetSymbolAddress((void**)&excl, g_excl);
    cudaGetSymbolAddress((void**)&bsums, g_bsums);

    const int eb = (N_EDGES + 255) / 256;
    const int nb = (N_NODES + 255) / 256;
    const int scan_blocks = (N_NODES + SCAN_BS - 1) / SCAN_BS;  // 196
    const int lin_blocks = (N_NODES + 7) / 8;

    // ---- Edge normalization + CSR build (once per launch) ----
    detect_dtype_kernel<<<1, 1>>>((const int*)ei);
    convert_edges_kernel<<<eb, 256>>>(ei, src, dst);
    zero_deg_kernel<<<nb, 256>>>(deg);
    histogram_kernel<<<eb, 256>>>(dst, deg);
    scan_partial_kernel<<<scan_blocks, SCAN_BS>>>(deg, excl, bsums);
    scan_bsums_kernel<<<1, 256>>>(bsums, scan_blocks);
    scan_finish_kernel<<<nb, 256>>>(excl, bsums, rowptr, cursor);
    bucket_scatter_kernel<<<eb, 256>>>(src, dst, cursor, csr_src);

    // ---- Layer 1 (F=50) ----
    csr_max_kernel<F_IN, 64><<<(N_NODES + 3) / 4, 256>>>(x, rowptr, deg, csr_src, agg);
    sage_linear_kernel<F_IN, true><<<lin_blocks, 256>>>(agg, x, Wl1, bl1, Wr1, h1);
    // ---- Layer 2 (F=32) ----
    csr_max_kernel<NC, 32><<<(N_NODES + 7) / 8, 256>>>(h1, rowptr, deg, csr_src, agg);
    sage_linear_kernel<NC, true><<<lin_blocks, 256>>>(agg, h1, Wl2, bl2, Wr2, h2);
    // ---- Layer 3 (F=32) + log_softmax ----
    csr_max_kernel<NC, 32><<<(N_NODES + 7) / 8, 256>>>(h2, rowptr, deg, csr_src, agg);
    sage_linear_lsm_kernel<NC><<<lin_blocks, 256>>>(agg, h2, Wl3, bl3, Wr3, out);
}

// round 5
// speedup vs baseline: 2.2016x; 1.1226x over previous
#include <cuda_runtime.h>
#include <math.h>

#define N_NODES 100000
#define N_EDGES 1600000
#define F_IN 50
#define NC 32
#define NEG_INF __int_as_float(0xFF800000)

// ---- Scratch (device globals — no allocation allowed) ----
__device__ int   g_csr_src[N_EDGES];
__device__ int   g_deg[N_NODES];
__device__ int   g_rowptr[N_NODES];
__device__ int   g_cursor[N_NODES];
__device__ int   g_excl[N_NODES];
__device__ int   g_bsums[256];
__device__ int   g_is64;
__device__ float g_h1[N_NODES * NC];
__device__ float g_h2[N_NODES * NC];

// ---- Edge dtype detection: one warp, ballot ----
__global__ void detect_dtype_kernel(const int* __restrict__ ei_raw) {
    // int64 little-endian with values < 2^31 -> every odd 32-bit word is 0
    int lane = threadIdx.x;
    int nz = (ei_raw[2 * lane + 1] != 0) | (ei_raw[2 * (lane + 32) + 1] != 0);
    unsigned any = __ballot_sync(0xffffffff, nz);
    if (lane == 0) g_is64 = (any == 0u);
}

__global__ void zero_deg_kernel(int* __restrict__ deg) {
    int i = blockIdx.x * blockDim.x + threadIdx.x;
    if (i < N_NODES) deg[i] = 0;
}

// histogram of dst, reading raw edge buffer directly
__global__ void histogram_kernel(const void* __restrict__ ei_raw, int* __restrict__ deg) {
    int i = blockIdx.x * blockDim.x + threadIdx.x;
    if (i >= N_EDGES) return;
    int d;
    if (g_is64) d = (int)((const long long*)ei_raw)[N_EDGES + i];
    else        d = ((const int*)ei_raw)[N_EDGES + i];
    atomicAdd(&deg[d], 1);
}

#define SCAN_BS 512
__global__ void scan_partial_kernel(const int* __restrict__ deg,
                                    int* __restrict__ excl, int* __restrict__ bsums) {
    __shared__ int s[SCAN_BS];
    int i = blockIdx.x * SCAN_BS + threadIdx.x;
    int v = (i < N_NODES) ? deg[i] : 0;
    s[threadIdx.x] = v;
    __syncthreads();
    for (int off = 1; off < SCAN_BS; off <<= 1) {
        int t = (threadIdx.x >= off) ? s[threadIdx.x - off] : 0;
        __syncthreads();
        s[threadIdx.x] += t;
        __syncthreads();
    }
    if (i < N_NODES) excl[i] = s[threadIdx.x] - v;
    if (threadIdx.x == SCAN_BS - 1) bsums[blockIdx.x] = s[SCAN_BS - 1];
}

__global__ void scan_bsums_kernel(int* __restrict__ bsums, int nb) {
    __shared__ int s[256];
    int t = threadIdx.x;
    s[t] = (t < nb) ? bsums[t] : 0;
    __syncthreads();
    if (t == 0) {
        int acc = 0;
        for (int i = 0; i < nb; i++) { int v = s[i]; s[i] = acc; acc += v; }
    }
    __syncthreads();
    if (t < nb) bsums[t] = s[t];
}

__global__ void scan_finish_kernel(const int* __restrict__ excl, const int* __restrict__ bsums,
                                   int* __restrict__ rowptr, int* __restrict__ cursor) {
    int i = blockIdx.x * blockDim.x + threadIdx.x;
    if (i >= N_NODES) return;
    int v = excl[i] + bsums[i / SCAN_BS];
    rowptr[i] = v;
    cursor[i] = v;
}

__global__ void bucket_scatter_kernel(const void* __restrict__ ei_raw,
                                      int* __restrict__ cursor, int* __restrict__ csr_src) {
    int i = blockIdx.x * blockDim.x + threadIdx.x;
    if (i >= N_EDGES) return;
    int s, d;
    if (g_is64) {
        const long long* p = (const long long*)ei_raw;
        s = (int)p[i];
        d = (int)p[N_EDGES + i];
    } else {
        const int* p = (const int*)ei_raw;
        s = p[i];
        d = p[N_EDGES + i];
    }
    int pos = atomicAdd(&cursor[d], 1);
    csr_src[pos] = s;
}

// ---- Layer 1 fused: gather-max (F=50) + linear + ReLU. 4 nodes/block. ----
__global__ void __launch_bounds__(256)
sage_layer1_kernel(const float* __restrict__ x,
                   const int* __restrict__ rowptr, const int* __restrict__ deg,
                   const int* __restrict__ csr_src,
                   const float* __restrict__ Wl, const float* __restrict__ bl,
                   const float* __restrict__ Wr,
                   float* __restrict__ out) {
    __shared__ float sWl[F_IN][NC];
    __shared__ float sWr[F_IN][NC];
    __shared__ float s_agg[4][F_IN + 2];
    __shared__ float s_part[8][NC];
    int tid = threadIdx.x;
    for (int i = tid; i < F_IN * NC; i += 256) {
        sWl[i / NC][i % NC] = Wl[i];
        sWr[i / NC][i % NC] = Wr[i];
    }

    // Phase 1: gather-max, 64 threads per node, lane f = feature
    int g = tid >> 6;            // 0..3 node slot
    int f = tid & 63;
    int node = blockIdx.x * 4 + g;
    {
        int start = rowptr[node];
        int d = deg[node];
        if (f < F_IN) {
            float v = NEG_INF;
            int j = 0;
            for (; j + 8 <= d; j += 8) {
                int s0 = csr_src[start + j + 0], s1 = csr_src[start + j + 1];
                int s2 = csr_src[start + j + 2], s3 = csr_src[start + j + 3];
                int s4 = csr_src[start + j + 4], s5 = csr_src[start + j + 5];
                int s6 = csr_src[start + j + 6], s7 = csr_src[start + j + 7];
                float a0 = x[s0 * F_IN + f], a1 = x[s1 * F_IN + f];
                float a2 = x[s2 * F_IN + f], a3 = x[s3 * F_IN + f];
                float a4 = x[s4 * F_IN + f], a5 = x[s5 * F_IN + f];
                float a6 = x[s6 * F_IN + f], a7 = x[s7 * F_IN + f];
                v = fmaxf(v, fmaxf(fmaxf(fmaxf(a0, a1), fmaxf(a2, a3)),
                                   fmaxf(fmaxf(a4, a5), fmaxf(a6, a7))));
            }
            for (; j < d; j++) v = fmaxf(v, x[csr_src[start + j] * F_IN + f]);
            s_agg[g][f] = (d == 0) ? 0.0f : v;
        }
    }
    __syncthreads();

    // Phase 2: linear. warp w: node w/2, k-half w&1, lane = col
    int w = tid >> 5;
    int c = tid & 31;
    int nl = w >> 1;
    int r = blockIdx.x * 4 + nl;
    int kbeg = (w & 1) * 25;
    const float* xr = x + r * F_IN;
    float acc = (w & 1) ? 0.0f : bl[c];   // bias added once per node
    #pragma unroll
    for (int k0 = 0; k0 < 25; k0++) {
        int k = kbeg + k0;
        acc += s_agg[nl][k] * sWl[k][c] + xr[k] * sWr[k][c];
    }
    s_part[w][c] = acc;
    __syncthreads();

    if (w < 4) {
        int rr = blockIdx.x * 4 + w;
        float v = s_part[2 * w][c] + s_part[2 * w + 1][c];
        out[rr * NC + c] = fmaxf(v, 0.0f);
    }
}

// ---- Layers 2/3 fused: warp per node. gather-max (F=32) + shuffle-GEMV. ----
template <bool RELU, bool LSM>
__global__ void __launch_bounds__(256)
sage_layer_f32_kernel(const float* __restrict__ hin,
                      const int* __restrict__ rowptr, const int* __restrict__ deg,
                      const int* __restrict__ csr_src,
                      const float* __restrict__ Wl, const float* __restrict__ bl,
                      const float* __restrict__ Wr,
                      float* __restrict__ out) {
    __shared__ float sWl[NC][NC];
    __shared__ float sWr[NC][NC];
    int tid = threadIdx.x;
    for (int i = tid; i < NC * NC; i += 256) {
        sWl[i / NC][i % NC] = Wl[i];
        sWr[i / NC][i % NC] = Wr[i];
    }

    int w = tid >> 5;
    int lane = tid & 31;
    int node = blockIdx.x * 8 + w;

    float bias = bl[lane];
    int start = rowptr[node];
    int d = deg[node];
    float xv = hin[node * NC + lane];
    __syncthreads();

    float v = NEG_INF;
    int j = 0;
    for (; j + 8 <= d; j += 8) {
        int s0 = csr_src[start + j + 0], s1 = csr_src[start + j + 1];
        int s2 = csr_src[start + j + 2], s3 = csr_src[start + j + 3];
        int s4 = csr_src[start + j + 4], s5 = csr_src[start + j + 5];
        int s6 = csr_src[start + j + 6], s7 = csr_src[start + j + 7];
        float a0 = hin[s0 * NC + lane], a1 = hin[s1 * NC + lane];
        float a2 = hin[s2 * NC + lane], a3 = hin[s3 * NC + lane];
        float a4 = hin[s4 * NC + lane], a5 = hin[s5 * NC + lane];
        float a6 = hin[s6 * NC + lane], a7 = hin[s7 * NC + lane];
        v = fmaxf(v, fmaxf(fmaxf(fmaxf(a0, a1), fmaxf(a2, a3)),
                           fmaxf(fmaxf(a4, a5), fmaxf(a6, a7))));
    }
    for (; j < d; j++) v = fmaxf(v, hin[csr_src[start + j] * NC + lane]);
    if (d == 0) v = 0.0f;

    // GEMV: acc_c = sum_k v_k*Wl[k][c] + x_k*Wr[k][c], c = lane
    float acc = bias;
#pragma unroll
    for (int k = 0; k < NC; k++) {
        float vk = __shfl_sync(0xffffffff, v, k);
        float xk = __shfl_sync(0xffffffff, xv, k);
        acc += vk * sWl[k][lane] + xk * sWr[k][lane];
    }

    if (RELU) acc = fmaxf(acc, 0.0f);
    if (LSM) {
        float m = acc;
#pragma unroll
        for (int o = 16; o; o >>= 1) m = fmaxf(m, __shfl_xor_sync(0xffffffff, m, o));
        float ex = __expf(acc - m);
        float s = ex;
#pragma unroll
        for (int o = 16; o; o >>= 1) s += __shfl_xor_sync(0xffffffff, s, o);
        acc = acc - m - __logf(s);
    }
    out[node * NC + lane] = acc;
}

extern "C" void kernel_launch(void* const* d_in, const int* in_sizes, int n_in,
                              void* d_out, int out_size) {
    const float* x = (const float*)d_in[0];
    const void* ei = d_in[1];
    const float* Wl1 = (const float*)d_in[2];
    const float* bl1 = (const float*)d_in[3];
    const float* Wr1 = (const float*)d_in[4];
    const float* Wl2 = (const float*)d_in[5];
    const float* bl2 = (const float*)d_in[6];
    const float* Wr2 = (const float*)d_in[7];
    const float* Wl3 = (const float*)d_in[8];
    const float* bl3 = (const float*)d_in[9];
    const float* Wr3 = (const float*)d_in[10];
    float* out = (float*)d_out;

    float *h1, *h2;
    int *csr_src, *deg, *rowptr, *cursor, *excl, *bsums;
    cudaGetSymbolAddress((void**)&h1, g_h1);
    cudaGetSymbolAddress((void**)&h2, g_h2);
    cudaGetSymbolAddress((void**)&csr_src, g_csr_src);
    cudaGetSymbolAddress((void**)&deg, g_deg);
    cudaGetSymbolAddress((void**)&rowptr, g_rowptr);
    cudaGetSymbolAddress((void**)&cursor, g_cursor);
    cudaGetSymbolAddress((void**)&excl, g_excl);
    cudaGetSymbolAddress((void**)&bsums, g_bsums);

    const int eb = (N_EDGES + 255) / 256;
    const int nb = (N_NODES + 255) / 256;
    const int scan_blocks = (N_NODES + SCAN_BS - 1) / SCAN_BS;  // 196

    // ---- CSR build directly from raw edge buffer ----
    detect_dtype_kernel<<<1, 32>>>((const int*)ei);
    zero_deg_kernel<<<nb, 256>>>(deg);
    histogram_kernel<<<eb, 256>>>(ei, deg);
    scan_partial_kernel<<<scan_blocks, SCAN_BS>>>(deg, excl, bsums);
    scan_bsums_kernel<<<1, 256>>>(bsums, scan_blocks);
    scan_finish_kernel<<<nb, 256>>>(excl, bsums, rowptr, cursor);
    bucket_scatter_kernel<<<eb, 256>>>(ei, cursor, csr_src);

    // ---- Fused layers ----
    sage_layer1_kernel<<<N_NODES / 4, 256>>>(x, rowptr, deg, csr_src, Wl1, bl1, Wr1, h1);
    sage_layer_f32_kernel<true, false><<<N_NODES / 8, 256>>>(h1, rowptr, deg, csr_src,
                                                             Wl2, bl2, Wr2, h2);
    sage_layer_f32_kernel<false, true><<<N_NODES / 8, 256>>>(h2, rowptr, deg, csr_src,
                                                             Wl3, bl3, Wr3, out);
}